// round 2
// baseline (speedup 1.0000x reference)
#include <cuda_runtime.h>

#define PI_F 3.14159265358979323846f

// ---------------------------------------------------------------------------
// Radial branch: per pair, 8 Gaussian-windowed cutoff features, scatter-added
// into aev[N_ATOMS*7, 8] at rows (i*7 + species_j) and (j*7 + species_i).
// Vector float4 atomics (sm_90+) -> RED.E.ADD.F32.V4; aev (11.2MB) stays in L2.
// ---------------------------------------------------------------------------
__global__ void ani_radial_kernel(const float* __restrict__ r_ij,
                                  const int*   __restrict__ pidx,
                                  const int*   __restrict__ an,
                                  float*       __restrict__ aev,
                                  int P)
{
    int p = blockIdx.x * blockDim.x + threadIdx.x;
    if (p >= P) return;

    float d  = r_ij[p];
    float fc = (d <= 5.1f) ? (0.5f * __cosf((PI_F / 5.1f) * d) + 0.5f) : 0.0f;

    float f[8];
#pragma unroll
    for (int k = 0; k < 8; k++) {
        float dd = d - (0.8f + 0.5375f * (float)k);     // ShfR[k]
        f[k] = 0.25f * __expf(-19.7f * dd * dd) * fc;
    }

    int i  = pidx[p];
    int j  = pidx[P + p];
    int si = an[i];
    int sj = an[j];

    float4 lo = make_float4(f[0], f[1], f[2], f[3]);
    float4 hi = make_float4(f[4], f[5], f[6], f[7]);

    float4* r0 = reinterpret_cast<float4*>(aev + ((long long)i * 7 + sj) * 8);
    float4* r1 = reinterpret_cast<float4*>(aev + ((long long)j * 7 + si) * 8);

    atomicAdd(r0,     lo);
    atomicAdd(r0 + 1, hi);
    atomicAdd(r1,     lo);
    atomicAdd(r1 + 1, hi);
}

// ---------------------------------------------------------------------------
// Angular branch: per triplet, 4x8 angular features. acos eliminated via
// cos(theta - Z) = cos_t*cosZ + sin_t*sinZ (theta in [0,pi] so sin >= 0).
// Output staged through smem (row stride 36 floats = 144B, 16B-aligned and
// bank-conflict-free for both STS.128 and LDS.128) then flushed as fully
// coalesced float4 stores.
// ---------------------------------------------------------------------------
__global__ void ani_angular_kernel(const float* __restrict__ vec12,
                                   float*       __restrict__ ang,
                                   int T)
{
    __shared__ float s[128][36];   // stride 36: 144B rows, 16B-aligned

    const int tid = threadIdx.x;
    const long long t = (long long)blockIdx.x * 128 + tid;

    float out[32];

    if (t < T) {
        const float* v1 = vec12 + 3LL * t;
        const float* v2 = vec12 + 3LL * T + 3LL * t;
        float x1 = v1[0], y1 = v1[1], z1 = v1[2];
        float x2 = v2[0], y2 = v2[1], z2 = v2[2];

        float d11 = fmaf(x1, x1, fmaf(y1, y1, z1 * z1));
        float d22 = fmaf(x2, x2, fmaf(y2, y2, z2 * z2));
        float d12 = fmaf(x1, x2, fmaf(y1, y2, z1 * z2));

        float rs1 = rsqrtf(d11);
        float rs2 = rsqrtf(d22);
        float d1  = d11 * rs1;
        float d2  = d22 * rs2;

        float cost = 0.95f * d12 * rs1 * rs2;                 // |cost| <= 0.95
        float sint = sqrtf(fmaxf(1.0f - cost * cost, 0.0f));  // theta in [0,pi]

        float fc1 = (d1 <= 3.5f) ? (0.5f * __cosf((PI_F / 3.5f) * d1) + 0.5f) : 0.0f;
        float fc2 = (d2 <= 3.5f) ? (0.5f * __cosf((PI_F / 3.5f) * d2) + 0.5f) : 0.0f;
        float fc2x = 2.0f * fc1 * fc2;

        float u = 0.5f * (d1 + d2);
        float frad[8];
#pragma unroll
        for (int a = 0; a < 8; a++) {
            float dd = u - (0.8f + 0.3375f * (float)a);   // ShfA[a]
            frad[a] = __expf(-12.5f * dd * dd);
        }

        // cos/sin of ShfZ = (z+0.5)*pi/4
        const float CZ[4] = { 0.9238795325f,  0.3826834324f, -0.3826834324f, -0.9238795325f };
        const float SZ[4] = { 0.3826834324f,  0.9238795325f,  0.9238795325f,  0.3826834324f };

#pragma unroll
        for (int z = 0; z < 4; z++) {
            float xz = 0.5f * (1.0f + cost * CZ[z] + sint * SZ[z]);   // in [0,1]
            float fang = (xz > 0.0f) ? __powf(xz, 14.1f) : 0.0f;
            fang *= fc2x;
#pragma unroll
            for (int a = 0; a < 8; a++)
                out[z * 8 + a] = fang * frad[a];
        }
    } else {
#pragma unroll
        for (int k = 0; k < 32; k++) out[k] = 0.0f;
    }

    // Stage to smem with float4 stores (row base 144B -> 16B aligned)
#pragma unroll
    for (int m = 0; m < 8; m++)
        *reinterpret_cast<float4*>(&s[tid][m * 4]) =
            *reinterpret_cast<const float4*>(&out[m * 4]);

    __syncthreads();

    // Coalesced flush: this block owns ang[base .. base + 128*32)
    const long long base  = (long long)blockIdx.x * (128 * 32);
    const long long limit = (long long)T * 32;
    float4* outv = reinterpret_cast<float4*>(ang + base);
#pragma unroll
    for (int j = tid; j < 128 * 8; j += 128) {
        if (base + (long long)j * 4 < limit) {
            int q = j >> 3;          // source row
            int k = (j & 7) << 2;    // source col (float index)
            outv[j] = *reinterpret_cast<const float4*>(&s[q][k]);
        }
    }
}

// ---------------------------------------------------------------------------
// Inputs (metadata order): r_ij f32[P], pair_indices i32[2,P],
// atomic_numbers i32[N_ATOMS], vec12 f32[2,T,3].
// Output: aev f32[N_ATOMS*7, 8] followed by ang f32[T, 32].
// ---------------------------------------------------------------------------
extern "C" void kernel_launch(void* const* d_in, const int* in_sizes, int n_in,
                              void* d_out, int out_size)
{
    const float* r_ij  = (const float*)d_in[0];
    const int*   pidx  = (const int*)  d_in[1];
    const int*   an    = (const int*)  d_in[2];
    const float* vec12 = (const float*)d_in[3];

    const int P = in_sizes[0];
    const int T = in_sizes[3] / 6;
    const long long aev_elems = (long long)in_sizes[2] * 7 * 8;

    float* aev = (float*)d_out;
    float* ang = aev + aev_elems;

    // aev must start at zero each replay (d_out is poisoned before timing)
    cudaMemsetAsync(d_out, 0, aev_elems * sizeof(float), 0);

    ani_radial_kernel<<<(P + 255) / 256, 256>>>(r_ij, pidx, an, aev, P);
    ani_angular_kernel<<<(T + 127) / 128, 128>>>(vec12, ang, T);
}

// round 3
// speedup vs baseline: 1.0447x; 1.0447x over previous
#include <cuda_runtime.h>

#define PI_F 3.14159265358979323846f

// ===========================================================================
// Fused kernel: even blocks do angular triplets (DRAM-write-bound), odd
// blocks do radial pairs (L2-atomic-bound). Co-residency overlaps the two
// bottlenecks instead of running them back-to-back.
// ===========================================================================
__global__ __launch_bounds__(128)
void ani_fused_kernel(const float* __restrict__ r_ij,
                      const int*   __restrict__ pidx,
                      const int*   __restrict__ an,
                      const float* __restrict__ vec12,
                      float*       __restrict__ aev,
                      float*       __restrict__ ang,
                      int P, int T, int A /*angular blocks*/, int R /*radial blocks*/)
{
    __shared__ float s[128][36];   // 144B rows: 16B-aligned, conflict-free

    const int tid = threadIdx.x;
    const int b   = blockIdx.x;

    // Interleave roles so both kinds are co-resident on every wave.
    int nboth = 2 * min(A, R);
    bool angular;
    int  idx;
    if (b < nboth) { angular = !(b & 1); idx = b >> 1; }
    else           { angular = (A > R);  idx = (b - nboth) + min(A, R); }

    if (angular) {
        // ----------------- angular branch -----------------
        const long long t = (long long)idx * 128 + tid;
        float out[32];

        if (t < T) {
            const float* v1 = vec12 + 3LL * t;
            const float* v2 = vec12 + 3LL * T + 3LL * t;
            float x1 = __ldcs(v1 + 0), y1 = __ldcs(v1 + 1), z1 = __ldcs(v1 + 2);
            float x2 = __ldcs(v2 + 0), y2 = __ldcs(v2 + 1), z2 = __ldcs(v2 + 2);

            float d11 = fmaf(x1, x1, fmaf(y1, y1, z1 * z1));
            float d22 = fmaf(x2, x2, fmaf(y2, y2, z2 * z2));
            float d12 = fmaf(x1, x2, fmaf(y1, y2, z1 * z2));

            float rs1 = rsqrtf(d11);
            float rs2 = rsqrtf(d22);
            float d1  = d11 * rs1;
            float d2  = d22 * rs2;

            float cost = 0.95f * d12 * rs1 * rs2;                 // |cost| <= 0.95
            float sint = sqrtf(fmaxf(1.0f - cost * cost, 0.0f));  // theta in [0,pi]

            float fc1 = (d1 <= 3.5f) ? (0.5f * __cosf((PI_F / 3.5f) * d1) + 0.5f) : 0.0f;
            float fc2 = (d2 <= 3.5f) ? (0.5f * __cosf((PI_F / 3.5f) * d2) + 0.5f) : 0.0f;
            float fc2x = 2.0f * fc1 * fc2;

            float u = 0.5f * (d1 + d2);
            float frad[8];
#pragma unroll
            for (int a = 0; a < 8; a++) {
                float dd = u - (0.8f + 0.3375f * (float)a);   // ShfA[a]
                frad[a] = __expf(-12.5f * dd * dd);
            }

            // cos/sin of ShfZ = (z+0.5)*pi/4
            const float CZ[4] = { 0.9238795325f,  0.3826834324f, -0.3826834324f, -0.9238795325f };
            const float SZ[4] = { 0.3826834324f,  0.9238795325f,  0.9238795325f,  0.3826834324f };

#pragma unroll
            for (int z = 0; z < 4; z++) {
                float xz = 0.5f * (1.0f + cost * CZ[z] + sint * SZ[z]);   // in [0,1]
                float fang = (xz > 0.0f) ? __powf(xz, 14.1f) : 0.0f;
                fang *= fc2x;
#pragma unroll
                for (int a = 0; a < 8; a++)
                    out[z * 8 + a] = fang * frad[a];
            }
        } else {
#pragma unroll
            for (int k = 0; k < 32; k++) out[k] = 0.0f;
        }

        // Stage to smem (STS.128), then flush fully coalesced with
        // evict-first stores: the 205MB output stream must not evict the
        // 11.2MB aev table the radial blocks are atomically updating in L2.
#pragma unroll
        for (int m = 0; m < 8; m++)
            *reinterpret_cast<float4*>(&s[tid][m * 4]) =
                *reinterpret_cast<const float4*>(&out[m * 4]);

        __syncthreads();

        const long long base  = (long long)idx * (128 * 32);
        const long long limit = (long long)T * 32;
        float4* outv = reinterpret_cast<float4*>(ang + base);
#pragma unroll
        for (int j = tid; j < 128 * 8; j += 128) {
            if (base + (long long)j * 4 < limit) {
                int q = j >> 3;
                int k = (j & 7) << 2;
                __stcs(&outv[j], *reinterpret_cast<const float4*>(&s[q][k]));
            }
        }
    } else {
        // ----------------- radial branch -----------------
        int p = idx * 128 + tid;
        if (p >= P) return;

        float d  = __ldcs(r_ij + p);
        float fc = (d <= 5.1f) ? (0.5f * __cosf((PI_F / 5.1f) * d) + 0.5f) : 0.0f;

        float f[8];
#pragma unroll
        for (int k = 0; k < 8; k++) {
            float dd = d - (0.8f + 0.5375f * (float)k);     // ShfR[k]
            f[k] = 0.25f * __expf(-19.7f * dd * dd) * fc;
        }

        int i  = pidx[p];
        int j  = pidx[P + p];
        int si = an[i];
        int sj = an[j];

        float4 lo = make_float4(f[0], f[1], f[2], f[3]);
        float4 hi = make_float4(f[4], f[5], f[6], f[7]);

        float4* r0 = reinterpret_cast<float4*>(aev + ((long long)i * 7 + sj) * 8);
        float4* r1 = reinterpret_cast<float4*>(aev + ((long long)j * 7 + si) * 8);

        atomicAdd(r0,     lo);
        atomicAdd(r0 + 1, hi);
        atomicAdd(r1,     lo);
        atomicAdd(r1 + 1, hi);
    }
}

// ---------------------------------------------------------------------------
// Inputs (metadata order): r_ij f32[P], pair_indices i32[2,P],
// atomic_numbers i32[N_ATOMS], vec12 f32[2,T,3].
// Output: aev f32[N_ATOMS*7, 8] followed by ang f32[T, 32].
// ---------------------------------------------------------------------------
extern "C" void kernel_launch(void* const* d_in, const int* in_sizes, int n_in,
                              void* d_out, int out_size)
{
    const float* r_ij  = (const float*)d_in[0];
    const int*   pidx  = (const int*)  d_in[1];
    const int*   an    = (const int*)  d_in[2];
    const float* vec12 = (const float*)d_in[3];

    const int P = in_sizes[0];
    const int T = in_sizes[3] / 6;
    const long long aev_elems = (long long)in_sizes[2] * 7 * 8;

    float* aev = (float*)d_out;
    float* ang = aev + aev_elems;

    const int A = (T + 127) / 128;   // angular blocks
    const int R = (P + 127) / 128;   // radial blocks

    // aev must start at zero each replay (d_out is poisoned before timing)
    cudaMemsetAsync(d_out, 0, aev_elems * sizeof(float), 0);

    ani_fused_kernel<<<A + R, 128>>>(r_ij, pidx, an, vec12, aev, ang, P, T, A, R);
}